// round 5
// baseline (speedup 1.0000x reference)
#include <cuda_runtime.h>

// Correlation cost volume, max_disp=4.
// out[b, dx*9+dy, h, w] = (1/128) * sum_c x1[b,c,h,w] * x2pad[b,c,h+dx,w+dy]
// x1,x2: [8,128,128,128] f32 ; out: [8,81,128,128] f32.
//
// R5 design: 8 px/thread (halves x2-window LDS redundancy), TH=4 rows/block,
// 16B XOR swizzle for conflict-free 32B-stride LDS.128, 3-stage cp.async pipe.

#define CC_C   128
#define CC_H   128
#define CC_W   128
#define CC_B   8
#define CC_D   4
#define CC_ND  9
#define CC_NOFF 81
#define CC_TH  4                      // output rows per block
#define CC_PX  8                      // pixels per thread
#define CC_CCH 8                      // channels per pipeline chunk
#define CC_NCHUNK (CC_C / CC_CCH)     // 16
#define CC_X2R (CC_TH + 2*CC_D)       // 12 padded x2 rows
#define CC_X2W (CC_W + 2*CC_D)        // 136 floats per padded row
#define NSTAGE 3
#define NTH    576   // 18 warps: warp=(dxi,half); lane: hl=half*2+(lane>>4), wg=lane&15

#define X1SF (CC_CCH*CC_TH*CC_W)      // 4096 floats / stage
#define X2SF (CC_CCH*CC_X2R*CC_X2W)   // 13056 floats / stage
#define STF  (X1SF + X2SF)            // 17152 floats / stage
#define STB  (STF * 4)                // 68608 bytes (mult of 128)
#define SMEM_BYTES (NSTAGE * STB)     // 205824 B

#define N_X1F4 (X1SF / 4)                      // 1024
#define N_X2F4 (CC_CCH * CC_X2R * (CC_W/4))    // 3072
#define N_FILL (N_X1F4 + N_X2F4)               // 4096
#define N_IT   8                               // fills per thread per chunk
#define CHUNK_SRC_BYTES (CC_CCH * CC_H * CC_W * 4)

typedef unsigned long long u64t;

#define FMA2(acc, a, b) \
    asm("fma.rn.f32x2 %0, %1, %2, %0;" : "+l"(acc) : "l"(a), "l"(b))
#define PACK2(d, lo, hi) \
    asm("mov.b64 %0, {%1, %2};" : "=l"(d) : "f"(lo), "f"(hi))
#define UNPACK2(lo, hi, v) \
    asm("mov.b64 {%0, %1}, %2;" : "=f"(lo), "=f"(hi) : "l"(v))

__device__ __forceinline__ void cp16(unsigned dst, const void* src, int src_bytes) {
    asm volatile("cp.async.cg.shared.global [%0], [%1], 16, %2;\n"
                 :: "r"(dst), "l"(src), "r"(src_bytes));
}

// 16B XOR swizzle: decollides 32B-stride LDS.128 phase patterns.
__device__ __forceinline__ unsigned swz(unsigned a) { return a ^ ((a >> 3) & 0x10u); }

__device__ __forceinline__ void issue_fills(unsigned smem_u32, unsigned stoff,
                                            const char* bx1, const char* bx2,
                                            unsigned coff, int tid, int h0)
{
#pragma unroll
    for (int k = 0; k < N_IT; ++k) {
        const int i = tid + k * NTH;
        if (i < N_X1F4) {
            const int c = i >> 7, rem = i & 127, hh = rem >> 5, q = rem & 31;
            const unsigned rel = (unsigned)((c * CC_TH + hh) * CC_W + 4 * q) * 4u;
            cp16(smem_u32 + stoff + swz(rel),
                 bx1 + ((size_t)(c * CC_H + h0 + hh) * CC_W + 4 * q) * 4 + coff, 16);
        } else if (i < N_FILL) {
            const int j = i - N_X1F4;
            const int c = j / (CC_X2R * 32), rem = j % (CC_X2R * 32);
            const int r = rem >> 5, q = rem & 31;
            const int grow = h0 - CC_D + r;
            const int ok = (grow >= 0) && (grow < CC_H);
            const unsigned rel =
                (unsigned)(X1SF + (c * CC_X2R + r) * CC_X2W + CC_D + 4 * q) * 4u;
            cp16(smem_u32 + stoff + swz(rel),
                 bx2 + ((size_t)(c * CC_H + (ok ? grow : 0)) * CC_W + 4 * q) * 4 + coff,
                 ok ? 16 : 0);
        }
    }
}

extern "C" __global__ void __launch_bounds__(NTH, 1)
corr_kernel(const float* __restrict__ x1,
            const float* __restrict__ x2,
            float* __restrict__ out)
{
    extern __shared__ char smem_c[];
    const int tid  = threadIdx.x;
    const int warp = tid >> 5;
    const int lane = tid & 31;
    const int dxi  = warp >> 1;                       // 0..8
    const int hl   = (warp & 1) * 2 + (lane >> 4);    // 0..3 : local output row
    const int wg   = lane & 15;                       // 16 groups of 8 px
    const int b    = blockIdx.y;
    const int h0   = blockIdx.x * CC_TH;

    unsigned smem_u32;
    asm("{ .reg .u64 t; cvta.to.shared.u64 t, %1; cvt.u32.u64 %0, t; }"
        : "=r"(smem_u32) : "l"(smem_c));

    // ---- zero left/right x2 pads once per stage (exactly 1 item/thread) ----
    {
        const int s = tid / (CC_CCH * CC_X2R * 2);       // stage
        const int rem = tid % (CC_CCH * CC_X2R * 2);
        const int cr = rem >> 1, side = rem & 1;
        const unsigned rel =
            (unsigned)(X1SF + cr * CC_X2W + (side ? (CC_D + CC_W) : 0)) * 4u;
        *(float4*)(smem_c + s * STB + swz(rel)) = make_float4(0.f, 0.f, 0.f, 0.f);
    }

    const char* bx1 = (const char*)(x1 + (size_t)b * CC_C * CC_H * CC_W);
    const char* bx2 = (const char*)(x2 + (size_t)b * CC_C * CC_H * CC_W);

    // ---- pipeline prologue: fill chunks 0,1 ----
#pragma unroll
    for (int pc = 0; pc < NSTAGE - 1; ++pc) {
        issue_fills(smem_u32, (unsigned)pc * STB, bx1, bx2,
                    (unsigned)pc * CHUNK_SRC_BYTES, tid, h0);
        asm volatile("cp.async.commit_group;");
    }

    u64t acc2[CC_ND][4] = {};   // 9 dy x 4 pixel-pairs (packed f32x2)

    for (int chunk = 0; chunk < CC_NCHUNK; ++chunk) {
        asm volatile("cp.async.wait_group 1;");
        __syncthreads();

        {   // fill chunk+2 into stage (chunk+2)%3
            const int fc = chunk + NSTAGE - 1;
            if (fc < CC_NCHUNK)
                issue_fills(smem_u32, (unsigned)(fc % NSTAGE) * STB, bx1, bx2,
                            (unsigned)fc * CHUNK_SRC_BYTES, tid, h0);
            asm volatile("cp.async.commit_group;");
        }

        const char* stc = smem_c + (chunk % NSTAGE) * STB;
        const unsigned x1rel0 =
            (unsigned)((hl)*CC_W + CC_PX * wg) * 4u;
        const unsigned x2rel0 =
            (unsigned)(X1SF + (hl + dxi) * CC_X2W + CC_PX * wg) * 4u;

#pragma unroll
        for (int c = 0; c < CC_CCH; ++c) {
            union { float4 f4[2]; float s[8];  u64t u[4]; } A;
            union { float4 f4[4]; float s[16]; u64t u[8]; } V;
            const unsigned x1rel = x1rel0 + (unsigned)(c * CC_TH * CC_W) * 4u;
            const unsigned x2rel = x2rel0 + (unsigned)(c * CC_X2R * CC_X2W) * 4u;
            A.f4[0] = *(const float4*)(stc + swz(x1rel));
            A.f4[1] = *(const float4*)(stc + swz(x1rel + 16u));
            V.f4[0] = *(const float4*)(stc + swz(x2rel));
            V.f4[1] = *(const float4*)(stc + swz(x2rel + 16u));
            V.f4[2] = *(const float4*)(stc + swz(x2rel + 32u));
            V.f4[3] = *(const float4*)(stc + swz(x2rel + 48u));

            u64t o[7];   // odd-parity window pairs
#pragma unroll
            for (int m = 0; m < 7; ++m)
                PACK2(o[m], V.s[2 * m + 1], V.s[2 * m + 2]);

            // even dy = 2t: acc[2t][j] += ap[j] * e[t+j]
#pragma unroll
            for (int t = 0; t < 5; ++t)
#pragma unroll
                for (int j = 0; j < 4; ++j)
                    FMA2(acc2[2 * t][j], A.u[j], V.u[t + j]);
            // odd dy = 2t+1: acc[2t+1][j] += ap[j] * o[t+j]
#pragma unroll
            for (int t = 0; t < 4; ++t)
#pragma unroll
                for (int j = 0; j < 4; ++j)
                    FMA2(acc2[2 * t + 1][j], A.u[j], o[t + j]);
        }
    }

    // ---- epilogue: scale by 1/C, store 9 x 2 float4 per thread ----
    const float inv = 1.0f / (float)CC_C;
    const int h = h0 + hl;
#pragma unroll
    for (int dy = 0; dy < CC_ND; ++dy) {
        float f[8];
#pragma unroll
        for (int j = 0; j < 4; ++j)
            UNPACK2(f[2 * j], f[2 * j + 1], acc2[dy][j]);
        float4 r0, r1;
        r0.x = f[0] * inv; r0.y = f[1] * inv; r0.z = f[2] * inv; r0.w = f[3] * inv;
        r1.x = f[4] * inv; r1.y = f[5] * inv; r1.z = f[6] * inv; r1.w = f[7] * inv;
        float* op = &out[(((size_t)(b * CC_NOFF + dxi * CC_ND + dy) * CC_H) + h) * CC_W
                         + CC_PX * wg];
        ((float4*)op)[0] = r0;
        ((float4*)op)[1] = r1;
    }
}

extern "C" void kernel_launch(void* const* d_in, const int* in_sizes, int n_in,
                              void* d_out, int out_size)
{
    const float* x1 = (const float*)d_in[0];
    const float* x2 = (const float*)d_in[1];
    float* out = (float*)d_out;

    cudaFuncSetAttribute(corr_kernel,
                         cudaFuncAttributeMaxDynamicSharedMemorySize, SMEM_BYTES);
    dim3 grid(CC_H / CC_TH, CC_B);   // (32, 8) = 256 blocks
    corr_kernel<<<grid, NTH, SMEM_BYTES>>>(x1, x2, out);
}

// round 6
// speedup vs baseline: 1.3718x; 1.3718x over previous
#include <cuda_runtime.h>

// Correlation cost volume, max_disp=4.
// out[b, dx*9+dy, h, w] = (1/128) * sum_c x1[b,c,h,w] * x2pad[b,c,h+dx,w+dy]
// x1,x2: [8,128,128,128] f32 ; out: [8,81,128,128] f32.
//
// R6: R4 design (TH=2, 4px/thread, 576 thr, packed f32x2) with CCH=16 and a
// 2-stage cp.async pipeline -> 8 barrier rounds instead of 16.

#define CC_C   128
#define CC_H   128
#define CC_W   128
#define CC_B   8
#define CC_D   4
#define CC_ND  9
#define CC_NOFF 81
#define CC_TH  2                      // output rows per block
#define CC_CCH 16                     // channels per pipeline chunk
#define CC_NCHUNK (CC_C / CC_CCH)     // 8
#define CC_X2R (CC_TH + 2*CC_D)       // 10 padded x2 rows
#define CC_X2W (CC_W + 2*CC_D)        // 136 floats per padded row
#define NSTAGE 2
#define NTH    576                    // 18 warps: warp = dxi + 9*hl; lane = 4px w-group

#define X1SF (CC_CCH*CC_TH*CC_W)      // 4096 floats / stage
#define X2SF (CC_CCH*CC_X2R*CC_X2W)   // 21760 floats / stage
#define STF  (X1SF + X2SF)            // 25856 floats / stage
#define STB  (STF * 4)                // 103424 B / stage
#define SMEM_BYTES (NSTAGE * STB)     // 206848 B

#define N_X1F4 (X1SF / 4)                      // 1024
#define N_X2F4 (CC_CCH * CC_X2R * (CC_W/4))    // 5120
#define N_FILL (N_X1F4 + N_X2F4)               // 6144 = 10.67/thread
#define CHUNK_SRC_BYTES (CC_CCH * CC_H * CC_W * 4)   // 1 MiB

typedef unsigned long long u64t;

union F4U { float4 f; u64t u[2]; float s[4]; };

#define FMA2(acc, a, b) \
    asm("fma.rn.f32x2 %0, %1, %2, %0;" : "+l"(acc) : "l"(a), "l"(b))
#define PACK2(d, lo, hi) \
    asm("mov.b64 %0, {%1, %2};" : "=l"(d) : "f"(lo), "f"(hi))
#define UNPACK2(lo, hi, v) \
    asm("mov.b64 {%0, %1}, %2;" : "=f"(lo), "=f"(hi) : "l"(v))

__device__ __forceinline__ void cp16(unsigned dst, const void* src, int src_bytes) {
    asm volatile("cp.async.cg.shared.global [%0], [%1], 16, %2;\n"
                 :: "r"(dst), "l"(src), "r"(src_bytes));
}

// Issue all fills for one chunk: runtime strided loop, indices recomputed
// (transient registers only -> no persistent pressure).
__device__ __forceinline__ void issue_fills(unsigned smem_u32, unsigned stoff,
                                            const char* bx1, const char* bx2,
                                            unsigned coff, int tid, int h0)
{
    for (int i = tid; i < N_FILL; i += NTH) {
        if (i < N_X1F4) {
            const int c = i >> 6, rem = i & 63, hh = rem >> 5, q = rem & 31;
            const unsigned dst = smem_u32 + stoff
                + (unsigned)((c * CC_TH + hh) * CC_W + 4 * q) * 4u;
            cp16(dst, bx1 + ((size_t)(c * CC_H + h0 + hh) * CC_W + 4 * q) * 4 + coff, 16);
        } else {
            const int j = i - N_X1F4;
            const int c = j / (CC_X2R * 32);
            const int rem = j - c * (CC_X2R * 32);
            const int r = rem >> 5, q = rem & 31;
            const int grow = h0 - CC_D + r;
            const int ok = (grow >= 0) && (grow < CC_H);
            const unsigned dst = smem_u32 + stoff
                + (unsigned)(X1SF + (c * CC_X2R + r) * CC_X2W + CC_D + 4 * q) * 4u;
            cp16(dst, bx2 + ((size_t)(c * CC_H + (ok ? grow : 0)) * CC_W + 4 * q) * 4 + coff,
                 ok ? 16 : 0);
        }
    }
}

extern "C" __global__ void __launch_bounds__(NTH, 1)
corr_kernel(const float* __restrict__ x1,
            const float* __restrict__ x2,
            float* __restrict__ out)
{
    extern __shared__ float smem[];
    const int tid  = threadIdx.x;
    const int warp = tid >> 5;
    const int lane = tid & 31;
    const int dxi  = warp % CC_ND;    // 0..8
    const int hl   = warp / CC_ND;    // 0..1
    const int b    = blockIdx.y;
    const int h0   = blockIdx.x * CC_TH;

    unsigned smem_u32;
    asm("{ .reg .u64 t; cvta.to.shared.u64 t, %1; cvt.u32.u64 %0, t; }"
        : "=r"(smem_u32) : "l"(smem));

    // ---- zero left/right x2 pads once per stage (never overwritten) ----
    for (int i = tid; i < NSTAGE * CC_CCH * CC_X2R * 2; i += NTH) {
        const int s    = i / (CC_CCH * CC_X2R * 2);
        const int rem  = i % (CC_CCH * CC_X2R * 2);
        const int cr   = rem >> 1;
        const int side = rem & 1;
        float* p = smem + s * STF + X1SF + cr * CC_X2W + (side ? (CC_D + CC_W) : 0);
        *(float4*)p = make_float4(0.f, 0.f, 0.f, 0.f);
    }

    const char* bx1 = (const char*)(x1 + (size_t)b * CC_C * CC_H * CC_W);
    const char* bx2 = (const char*)(x2 + (size_t)b * CC_C * CC_H * CC_W);

    // ---- prologue: fill chunk 0 into stage 0 ----
    issue_fills(smem_u32, 0u, bx1, bx2, 0u, tid, h0);
    asm volatile("cp.async.commit_group;");

    u64t acc2[CC_ND][2] = {};   // 9 dy x 2 pixel-pairs (packed f32x2)

    for (int chunk = 0; chunk < CC_NCHUNK; ++chunk) {
        asm volatile("cp.async.wait_group 0;");   // chunk's fill complete
        __syncthreads();                           // + everyone done with prev stage

        {   // fill chunk+1 into the other stage; overlaps compute below
            const int fc = chunk + 1;
            if (fc < CC_NCHUNK)
                issue_fills(smem_u32, (unsigned)(fc & 1) * STB, bx1, bx2,
                            (unsigned)fc * CHUNK_SRC_BYTES, tid, h0);
            asm volatile("cp.async.commit_group;");
        }

        const float* stp = smem + (chunk & 1) * STF;
        const float* x1p = stp + hl * CC_W + 4 * lane;
        const float* x2p = stp + X1SF + (hl + dxi) * CC_X2W + 4 * lane;

#pragma unroll
        for (int c = 0; c < CC_CCH; ++c) {
            F4U A, V0, V1, V2;
            A.f  = *(const float4*)(x1p + c * CC_TH * CC_W);
            V0.f = *(const float4*)(x2p + c * CC_X2R * CC_X2W);
            V1.f = *(const float4*)(x2p + c * CC_X2R * CC_X2W + 4);
            V2.f = *(const float4*)(x2p + c * CC_X2R * CC_X2W + 8);

            const u64t ap0 = A.u[0], ap1 = A.u[1];
            const u64t e0 = V0.u[0], e1 = V0.u[1];
            const u64t e2 = V1.u[0], e3 = V1.u[1];
            const u64t e4 = V2.u[0], e5 = V2.u[1];
            u64t o0, o1, o2, o3, o4;   // odd-parity window pairs: 5 packs
            PACK2(o0, V0.s[1], V0.s[2]);
            PACK2(o1, V0.s[3], V1.s[0]);
            PACK2(o2, V1.s[1], V1.s[2]);
            PACK2(o3, V1.s[3], V2.s[0]);
            PACK2(o4, V2.s[1], V2.s[2]);

            FMA2(acc2[0][0], ap0, e0); FMA2(acc2[0][1], ap1, e1);
            FMA2(acc2[2][0], ap0, e1); FMA2(acc2[2][1], ap1, e2);
            FMA2(acc2[4][0], ap0, e2); FMA2(acc2[4][1], ap1, e3);
            FMA2(acc2[6][0], ap0, e3); FMA2(acc2[6][1], ap1, e4);
            FMA2(acc2[8][0], ap0, e4); FMA2(acc2[8][1], ap1, e5);
            FMA2(acc2[1][0], ap0, o0); FMA2(acc2[1][1], ap1, o1);
            FMA2(acc2[3][0], ap0, o1); FMA2(acc2[3][1], ap1, o2);
            FMA2(acc2[5][0], ap0, o2); FMA2(acc2[5][1], ap1, o3);
            FMA2(acc2[7][0], ap0, o3); FMA2(acc2[7][1], ap1, o4);
        }
    }

    // ---- epilogue: scale by 1/C, store 9 float4 per thread ----
    const float inv = 1.0f / (float)CC_C;
    const int h = h0 + hl;
#pragma unroll
    for (int dy = 0; dy < CC_ND; ++dy) {
        float f0, f1, f2, f3;
        UNPACK2(f0, f1, acc2[dy][0]);
        UNPACK2(f2, f3, acc2[dy][1]);
        float4 r;
        r.x = f0 * inv; r.y = f1 * inv; r.z = f2 * inv; r.w = f3 * inv;
        *(float4*)&out[(((size_t)(b * CC_NOFF + dxi * CC_ND + dy) * CC_H) + h) * CC_W + 4 * lane] = r;
    }
}

extern "C" void kernel_launch(void* const* d_in, const int* in_sizes, int n_in,
                              void* d_out, int out_size)
{
    const float* x1 = (const float*)d_in[0];
    const float* x2 = (const float*)d_in[1];
    float* out = (float*)d_out;

    cudaFuncSetAttribute(corr_kernel,
                         cudaFuncAttributeMaxDynamicSharedMemorySize, SMEM_BYTES);
    dim3 grid(CC_H / CC_TH, CC_B);   // (64, 8) = 512 blocks
    corr_kernel<<<grid, NTH, SMEM_BYTES>>>(x1, x2, out);
}

// round 7
// speedup vs baseline: 1.4087x; 1.0269x over previous
#include <cuda_runtime.h>

// Correlation cost volume, max_disp=4.
// out[b, dx*9+dy, h, w] = (1/128) * sum_c x1[b,c,h,w] * x2pad[b,c,h+dx,w+dy]
// x1,x2: [8,128,128,128] f32 ; out: [8,81,128,128] f32.
//
// R7: warp-specialized producer/consumer with mbarrier pipeline.
//   18 compute warps (dxi x hl, 4px/thread, packed f32x2), 2 producer warps
//   doing all cp.async fills. 2 stages x 16 channels. No __syncthreads in loop.

#define CC_C   128
#define CC_H   128
#define CC_W   128
#define CC_B   8
#define CC_D   4
#define CC_ND  9
#define CC_NOFF 81
#define CC_TH  2
#define CC_CCH 16
#define CC_NCHUNK (CC_C / CC_CCH)     // 8
#define CC_X2R (CC_TH + 2*CC_D)       // 10
#define CC_X2W (CC_W + 2*CC_D)        // 136
#define NSTAGE 2
#define NCW    18                     // compute warps
#define NPT    64                     // producer threads (2 warps)
#define NTH    (NCW*32 + NPT)         // 640

#define X1SF (CC_CCH*CC_TH*CC_W)      // 4096 floats / stage
#define X2SF (CC_CCH*CC_X2R*CC_X2W)   // 21760 floats / stage
#define STF  (X1SF + X2SF)            // 25856 floats / stage
#define STB  (STF * 4)                // 103424 B
#define DATAB 64                      // byte offset of stage data (mbarriers first)
#define SMEM_BYTES (DATAB + NSTAGE * STB)   // 206912 B

#define N_X1F4 (X1SF / 4)                    // 1024
#define N_X2F4 (CC_CCH * CC_X2R * (CC_W/4))  // 5120
#define CHUNK_SRC_BYTES (CC_CCH * CC_H * CC_W * 4)

// mbarrier byte offsets within smem
#define MB_FULL(s)  ((s) * 8)
#define MB_EMPTY(s) (16 + (s) * 8)

typedef unsigned long long u64t;
union F4U { float4 f; u64t u[2]; float s[4]; };

#define FMA2(acc, a, b) \
    asm("fma.rn.f32x2 %0, %1, %2, %0;" : "+l"(acc) : "l"(a), "l"(b))
#define PACK2(d, lo, hi) \
    asm("mov.b64 %0, {%1, %2};" : "=l"(d) : "f"(lo), "f"(hi))
#define UNPACK2(lo, hi, v) \
    asm("mov.b64 {%0, %1}, %2;" : "=f"(lo), "=f"(hi) : "l"(v))

__device__ __forceinline__ void cp16(unsigned dst, const void* src, int src_bytes) {
    asm volatile("cp.async.cg.shared.global [%0], [%1], 16, %2;\n"
                 :: "r"(dst), "l"(src), "r"(src_bytes));
}

__device__ __forceinline__ void mbar_init(unsigned addr, unsigned cnt) {
    asm volatile("mbarrier.init.shared.b64 [%0], %1;" :: "r"(addr), "r"(cnt) : "memory");
}
__device__ __forceinline__ void mbar_arrive(unsigned addr) {
    asm volatile("mbarrier.arrive.shared.b64 _, [%0];" :: "r"(addr) : "memory");
}
__device__ __forceinline__ void cpasync_arrive_noinc(unsigned addr) {
    asm volatile("cp.async.mbarrier.arrive.noinc.shared::cta.b64 [%0];"
                 :: "r"(addr) : "memory");
}
// acquire wait (consumers: generic LDS after wait)
__device__ __forceinline__ void mbar_wait_acq(unsigned addr, unsigned parity) {
    asm volatile(
        "{\n\t"
        ".reg .pred P;\n\t"
        "WL_%=:\n\t"
        "mbarrier.try_wait.parity.acquire.cta.shared::cta.b64 P, [%0], %1, 0x989680;\n\t"
        "@P bra.uni WD_%=;\n\t"
        "bra.uni WL_%=;\n\t"
        "WD_%=:\n\t"
        "}" :: "r"(addr), "r"(parity) : "memory");
}
// relaxed wait (producers: post-wait accesses are async-proxy cp.async)
__device__ __forceinline__ void mbar_wait_rlx(unsigned addr, unsigned parity) {
    asm volatile(
        "{\n\t"
        ".reg .pred P;\n\t"
        "WL_%=:\n\t"
        "mbarrier.try_wait.parity.relaxed.cta.shared::cta.b64 P, [%0], %1, 0x989680;\n\t"
        "@P bra.uni WD_%=;\n\t"
        "bra.uni WL_%=;\n\t"
        "WD_%=:\n\t"
        "}" :: "r"(addr), "r"(parity) : "memory");
}

__device__ __forceinline__ void producer_fill(unsigned smem_u32, unsigned stoff,
                                              const char* bx1, const char* bx2,
                                              unsigned coff, int ptid, int h0)
{
    // x1: 1024 items, 16 per producer thread
#pragma unroll 4
    for (int i = ptid; i < N_X1F4; i += NPT) {
        const int c = i >> 6, rem = i & 63, hh = rem >> 5, q = rem & 31;
        cp16(smem_u32 + stoff + (unsigned)((c * CC_TH + hh) * CC_W + 4 * q) * 4u,
             bx1 + ((size_t)(c * CC_H + h0 + hh) * CC_W + 4 * q) * 4 + coff, 16);
    }
    // x2: 5120 items, 80 per producer thread
#pragma unroll 4
    for (int j = ptid; j < N_X2F4; j += NPT) {
        const int c = j / (CC_X2R * 32);
        const int rem = j - c * (CC_X2R * 32);
        const int r = rem >> 5, q = rem & 31;
        const int grow = h0 - CC_D + r;
        const int ok = (grow >= 0) && (grow < CC_H);
        cp16(smem_u32 + stoff +
                 (unsigned)(X1SF + (c * CC_X2R + r) * CC_X2W + CC_D + 4 * q) * 4u,
             bx2 + ((size_t)(c * CC_H + (ok ? grow : 0)) * CC_W + 4 * q) * 4 + coff,
             ok ? 16 : 0);
    }
}

extern "C" __global__ void __launch_bounds__(NTH, 1)
corr_kernel(const float* __restrict__ x1,
            const float* __restrict__ x2,
            float* __restrict__ out)
{
    extern __shared__ float smem[];
    float* data = smem + (DATAB / 4);
    const int tid = threadIdx.x;
    const int b   = blockIdx.y;
    const int h0  = blockIdx.x * CC_TH;

    unsigned smem_u32;
    asm("{ .reg .u64 t; cvta.to.shared.u64 t, %1; cvt.u32.u64 %0, t; }"
        : "=r"(smem_u32) : "l"(smem));

    // ---- init mbarriers ----
    if (tid == 0) {
        mbar_init(smem_u32 + MB_FULL(0), NPT);
        mbar_init(smem_u32 + MB_FULL(1), NPT);
        mbar_init(smem_u32 + MB_EMPTY(0), NCW * 32);
        mbar_init(smem_u32 + MB_EMPTY(1), NCW * 32);
    }

    // ---- zero left/right x2 pads once per stage: exactly 1 item/thread ----
    {
        const int s = tid / (CC_CCH * CC_X2R * 2);       // NSTAGE*16*10*2 == 640
        const int rem = tid % (CC_CCH * CC_X2R * 2);
        const int cr = rem >> 1, side = rem & 1;
        float* p = data + s * STF + X1SF + cr * CC_X2W + (side ? (CC_D + CC_W) : 0);
        *(float4*)p = make_float4(0.f, 0.f, 0.f, 0.f);
    }
    __syncthreads();   // mbarrier init + pads visible to everyone

    const char* bx1 = (const char*)(x1 + (size_t)b * CC_C * CC_H * CC_W);
    const char* bx2 = (const char*)(x2 + (size_t)b * CC_C * CC_H * CC_W);

    if (tid >= NCW * 32) {
        // ================= PRODUCER (2 warps) =================
        const int ptid = tid - NCW * 32;
        unsigned eph0 = 1, eph1 = 1;   // flipped phase: first waits pass immediately
        for (int fc = 0; fc < CC_NCHUNK; ++fc) {
            const int s = fc & 1;
            if (s) { mbar_wait_rlx(smem_u32 + MB_EMPTY(1), eph1); eph1 ^= 1; }
            else   { mbar_wait_rlx(smem_u32 + MB_EMPTY(0), eph0); eph0 ^= 1; }
            producer_fill(smem_u32, DATAB + (unsigned)s * STB, bx1, bx2,
                          (unsigned)fc * CHUNK_SRC_BYTES, ptid, h0);
            cpasync_arrive_noinc(smem_u32 + MB_FULL(s));
        }
        return;
    }

    // ================= CONSUMER (18 warps) =================
    const int warp = tid >> 5;
    const int lane = tid & 31;
    const int dxi  = warp % CC_ND;    // 0..8
    const int hl   = warp / CC_ND;    // 0..1

    u64t acc2[CC_ND][2] = {};
    unsigned fph0 = 0, fph1 = 0;

    for (int chunk = 0; chunk < CC_NCHUNK; ++chunk) {
        const int s = chunk & 1;
        if (s) { mbar_wait_acq(smem_u32 + MB_FULL(1), fph1); fph1 ^= 1; }
        else   { mbar_wait_acq(smem_u32 + MB_FULL(0), fph0); fph0 ^= 1; }

        const float* stp = data + s * STF;
        const float* x1p = stp + hl * CC_W + 4 * lane;
        const float* x2p = stp + X1SF + (hl + dxi) * CC_X2W + 4 * lane;

#pragma unroll
        for (int c = 0; c < CC_CCH; ++c) {
            F4U A, V0, V1, V2;
            A.f  = *(const float4*)(x1p + c * CC_TH * CC_W);
            V0.f = *(const float4*)(x2p + c * CC_X2R * CC_X2W);
            V1.f = *(const float4*)(x2p + c * CC_X2R * CC_X2W + 4);
            V2.f = *(const float4*)(x2p + c * CC_X2R * CC_X2W + 8);

            const u64t ap0 = A.u[0], ap1 = A.u[1];
            const u64t e0 = V0.u[0], e1 = V0.u[1];
            const u64t e2 = V1.u[0], e3 = V1.u[1];
            const u64t e4 = V2.u[0], e5 = V2.u[1];
            u64t o0, o1, o2, o3, o4;
            PACK2(o0, V0.s[1], V0.s[2]);
            PACK2(o1, V0.s[3], V1.s[0]);
            PACK2(o2, V1.s[1], V1.s[2]);
            PACK2(o3, V1.s[3], V2.s[0]);
            PACK2(o4, V2.s[1], V2.s[2]);

            FMA2(acc2[0][0], ap0, e0); FMA2(acc2[0][1], ap1, e1);
            FMA2(acc2[2][0], ap0, e1); FMA2(acc2[2][1], ap1, e2);
            FMA2(acc2[4][0], ap0, e2); FMA2(acc2[4][1], ap1, e3);
            FMA2(acc2[6][0], ap0, e3); FMA2(acc2[6][1], ap1, e4);
            FMA2(acc2[8][0], ap0, e4); FMA2(acc2[8][1], ap1, e5);
            FMA2(acc2[1][0], ap0, o0); FMA2(acc2[1][1], ap1, o1);
            FMA2(acc2[3][0], ap0, o1); FMA2(acc2[3][1], ap1, o2);
            FMA2(acc2[5][0], ap0, o2); FMA2(acc2[5][1], ap1, o3);
            FMA2(acc2[7][0], ap0, o3); FMA2(acc2[7][1], ap1, o4);
        }
        // loads consumed (in-order issue: FMAs above depend on them) -> release stage
        if (s) mbar_arrive(smem_u32 + MB_EMPTY(1));
        else   mbar_arrive(smem_u32 + MB_EMPTY(0));
    }

    // ---- epilogue: scale by 1/C, store 9 float4 per thread ----
    const float inv = 1.0f / (float)CC_C;
    const int h = h0 + hl;
#pragma unroll
    for (int dy = 0; dy < CC_ND; ++dy) {
        float f0, f1, f2, f3;
        UNPACK2(f0, f1, acc2[dy][0]);
        UNPACK2(f2, f3, acc2[dy][1]);
        float4 r;
        r.x = f0 * inv; r.y = f1 * inv; r.z = f2 * inv; r.w = f3 * inv;
        *(float4*)&out[(((size_t)(b * CC_NOFF + dxi * CC_ND + dy) * CC_H) + h) * CC_W
                       + 4 * lane] = r;
    }
}

extern "C" void kernel_launch(void* const* d_in, const int* in_sizes, int n_in,
                              void* d_out, int out_size)
{
    const float* x1 = (const float*)d_in[0];
    const float* x2 = (const float*)d_in[1];
    float* out = (float*)d_out;

    cudaFuncSetAttribute(corr_kernel,
                         cudaFuncAttributeMaxDynamicSharedMemorySize, SMEM_BYTES);
    dim3 grid(CC_H / CC_TH, CC_B);   // (64, 8) = 512 blocks
    corr_kernel<<<grid, NTH, SMEM_BYTES>>>(x1, x2, out);
}